// round 7
// baseline (speedup 1.0000x reference)
#include <cuda_runtime.h>
#include <math.h>

// RoIPooling, single persistent kernel with internal grid barriers.
// feat [B,C,50,50] f32, rois [N,5] f32, img scalars -> out [N,C,7,7] f32.
// Bench: B=2, C=256, N=128, IMG=800.
//
// Phase 1: feat[b][c][p] -> g_featT[b][p][c] (float4 smem-tiled transpose),
//          plus per-bin bounds table g_bintab (one FDIV chain per bin total).
// Phase 2: warp per (bin, c-half): warp-private smem offset table, flat
//          unrolled float4 load loop, coalesced writes to g_outT[bin][c].
// Phase 3: block per roi: g_outT[n][q][c] -> out[n][c][q], smem staged,
//          coalesced on both sides (two c-half passes).
// Grid barriers: monotonic ticket barrier (graph-replay safe, never reset).

#define C_DIM 256
#define FH 50
#define FW 50
#define NPIX (FH * FW)
#define OH 7
#define OW 7
#define QD (OH * OW)
#define MAX_B 4
#define MAX_ROIS 512
#define NBLK 148
#define NTHR 512
#define NWARP (NTHR / 32)

__device__ float g_featT[MAX_B * NPIX * C_DIM];     // [b][p][c]
__device__ float g_outT[MAX_ROIS * QD * C_DIM];     // [bin][c]
__device__ int2  g_bintab[MAX_ROIS * QD];           // {packed ys|ye|xs|xe, plane base}
__device__ unsigned g_bar;                          // monotonic ticket counter (zero-init)

__device__ __forceinline__ float decode_dim(const void* p) {
    int v = *reinterpret_cast<const int*>(p);
    if (v > 0 && v < 1000000) return (float)v;   // int scalar (800 = 0x320)
    return __int_as_float(v);                     // float bits
}

__device__ __forceinline__ void grid_barrier() {
    __syncthreads();
    __shared__ unsigned s_tgt;
    if (threadIdx.x == 0) {
        __threadfence();                                  // release prior writes
        unsigned ticket = atomicAdd(&g_bar, 1u);
        s_tgt = (ticket / NBLK + 1u) * NBLK;
    }
    __syncthreads();
    if (threadIdx.x == 0) {
        unsigned tgt = s_tgt;
        while (*((volatile unsigned*)&g_bar) < tgt) { }
        __threadfence();                                  // acquire others' writes
    }
    __syncthreads();
}

__device__ __forceinline__ float4 f4max(float4 a, float4 b) {
    return make_float4(fmaxf(a.x, b.x), fmaxf(a.y, b.y),
                       fmaxf(a.z, b.z), fmaxf(a.w, b.w));
}

__global__ void __launch_bounds__(NTHR, 1)
roipool_all(const float* __restrict__ feat,
            const float* __restrict__ rois,
            const void* __restrict__ img_h_p,
            const void* __restrict__ img_w_p,
            float* __restrict__ out,
            int B, int nrois) {
    // union scratch: phase1 uses 2 tiles of 32x33 f32 (8.4 KB); phase3 uses 49x129 f32 (25.3 KB)
    __shared__ __align__(16) float s_mem[QD * 129];
    __shared__ int s_offs[NWARP][64];

    int tid = threadIdx.x;
    int bid = blockIdx.x;
    int nbins = nrois * QD;

    // ---------------- Phase 1a: bintab (bounds per bin, computed once) ----------------
    {
        int g = bid * NTHR + tid;
        if (g < nbins) {
            int ow = g % OW;
            int oh = (g / OW) % OH;
            int n  = g / QD;

            float img_h = decode_dim(img_h_p);
            float img_w = decode_dim(img_w_p);
            float sh = __fdiv_rn((float)FH, img_h);
            float sw = __fdiv_rn((float)FW, img_w);

            const float* r = rois + n * 5;
            int bidx = (int)r[0];
            // exact reference rounding: single rn-multiply, floor, clamps
            int x1 = max((int)floorf(__fmul_rn(r[1], sw)), 0);
            int y1 = max((int)floorf(__fmul_rn(r[2], sh)), 0);
            int x2 = min((int)floorf(__fmul_rn(r[3], sw)), FW);
            int y2 = min((int)floorf(__fmul_rn(r[4], sh)), FH);

            float bh = __fdiv_rn((float)max(y2 - y1, 1), (float)OH);
            float bw = __fdiv_rn((float)max(x2 - x1, 1), (float)OW);
            float y1f = (float)y1, x1f = (float)x1;
            // mul then add, each correctly rounded (no FMA contraction) — matches jnp
            int ys = (int)floorf(__fadd_rn(y1f, __fmul_rn((float)oh,       bh)));
            int ye = (int)floorf(__fadd_rn(y1f, __fmul_rn((float)(oh + 1), bh)));
            int xs = (int)floorf(__fadd_rn(x1f, __fmul_rn((float)ow,       bw)));
            int xe = (int)floorf(__fadd_rn(x1f, __fmul_rn((float)(ow + 1), bw)));
            ys = min(max(ys, 0), FH - 1);
            ye = min(max(ye, 0), FH);
            xs = min(max(xs, 0), FW - 1);
            xe = min(max(xe, 0), FW);

            g_bintab[g] = make_int2(ys | (ye << 8) | (xs << 16) | (xe << 24),
                                    bidx * (NPIX * C_DIM));
        }
    }

    // ---------------- Phase 1b: transpose feat -> featT ----------------
    {
        float* tile = s_mem + (tid >> 8) * (32 * 33);   // two 256-thread halves
        int u = tid & 255;
        const int pxt = (NPIX + 31) / 32;               // 79
        const int ct  = C_DIM / 32;                     // 8
        int tiles = pxt * ct * B;
        int pairs = (tiles + 1) >> 1;
        int rounds = (pairs + NBLK - 1) / NBLK;

        for (int rnd = 0; rnd < rounds; ++rnd) {
            int t = (bid + rnd * NBLK) * 2 + (tid >> 8);
            bool act = t < tiles;
            int pt = 0, cti = 0, b = 0;
            if (act) {
                pt  = t % pxt;
                cti = (t / pxt) % ct;
                b   = t / (pxt * ct);
            }
            int p0 = pt * 32, c0 = cti * 32;

            if (act) {
                int cl = u >> 3;
                int pq = (u & 7) << 2;
                int p = p0 + pq;
                if (p < NPIX) {   // NPIX%4==0, p%4==0 -> p+3 < NPIX
                    float4 v = *reinterpret_cast<const float4*>(
                        feat + ((size_t)(b * C_DIM + c0 + cl)) * NPIX + p);
                    tile[cl * 33 + pq + 0] = v.x;
                    tile[cl * 33 + pq + 1] = v.y;
                    tile[cl * 33 + pq + 2] = v.z;
                    tile[cl * 33 + pq + 3] = v.w;
                }
            }
            __syncthreads();
            if (act) {
                int pl = u >> 3;
                int p = p0 + pl;
                if (p < NPIX) {
                    int cq = (u & 7) << 2;
                    float4 v;
                    v.x = tile[(cq + 0) * 33 + pl];
                    v.y = tile[(cq + 1) * 33 + pl];
                    v.z = tile[(cq + 2) * 33 + pl];
                    v.w = tile[(cq + 3) * 33 + pl];
                    *reinterpret_cast<float4*>(
                        g_featT + ((size_t)b * NPIX + p) * C_DIM + c0 + cq) = v;
                }
            }
            __syncthreads();
        }
    }

    grid_barrier();

    // ---------------- Phase 2: pooling; warp per (bin, c-half) ----------------
    {
        int w = tid >> 5;
        int lane = tid & 31;
        int gw = bid * NWARP + w;
        int units = nbins * 2;
        const int stride = NBLK * NWARP;   // 2368

        for (int u = gw; u < units; u += stride) {
            int bin = u >> 1;
            int chalf = u & 1;

            int2 e = g_bintab[bin];
            int pb = e.x;
            int ys =  pb        & 0xFF;
            int ye = (pb >> 8)  & 0xFF;
            int xs = (pb >> 16) & 0xFF;
            int xe = (pb >> 24) & 0xFF;
            int rows = ye - ys;
            int cols = xe - xs;
            int count = (rows > 0 && cols > 0) ? rows * cols : 0;   // <= 64

            __syncwarp();
            if (lane < count) {
                int yy = ys + lane / cols;
                int xx = xs + lane % cols;
                s_offs[w][lane] = (yy * FW + xx) * C_DIM;
            }
            if (count > 32 && lane + 32 < count) {
                int l2 = lane + 32;
                int yy = ys + l2 / cols;
                int xx = xs + l2 % cols;
                s_offs[w][l2] = (yy * FW + xx) * C_DIM;
            }
            __syncwarp();

            const float* base = g_featT + e.y + chalf * 128 + lane * 4;

            float4 m = make_float4(-INFINITY, -INFINITY, -INFINITY, -INFINITY);
            int i = 0;
            for (; i + 4 <= count; i += 4) {
                float4 a0 = *reinterpret_cast<const float4*>(base + s_offs[w][i + 0]);
                float4 a1 = *reinterpret_cast<const float4*>(base + s_offs[w][i + 1]);
                float4 a2 = *reinterpret_cast<const float4*>(base + s_offs[w][i + 2]);
                float4 a3 = *reinterpret_cast<const float4*>(base + s_offs[w][i + 3]);
                m = f4max(m, f4max(f4max(a0, a1), f4max(a2, a3)));
            }
            for (; i < count; ++i) {
                m = f4max(m, *reinterpret_cast<const float4*>(base + s_offs[w][i]));
            }
            if (count == 0) m = make_float4(0.f, 0.f, 0.f, 0.f);

            *reinterpret_cast<float4*>(
                g_outT + (size_t)bin * C_DIM + chalf * 128 + lane * 4) = m;
        }
    }

    grid_barrier();

    // ---------------- Phase 3: outT [n][q][c] -> out [n][c][q] ----------------
    {
        int rounds = (nrois + NBLK - 1) / NBLK;
        for (int rnd = 0; rnd < rounds; ++rnd) {
            int n = bid + rnd * NBLK;
            bool act = n < nrois;
            #pragma unroll
            for (int h = 0; h < 2; ++h) {
                if (act) {
                    const float* src = g_outT + (size_t)n * (QD * C_DIM) + h * 128;
                    for (int i = tid; i < QD * 128; i += NTHR) {
                        int q  = i >> 7;
                        int cl = i & 127;
                        s_mem[q * 129 + cl] = src[(size_t)q * C_DIM + cl];  // coalesced
                    }
                }
                __syncthreads();
                if (act) {
                    float* dst = out + (size_t)n * (C_DIM * QD) + (size_t)h * 128 * QD;
                    for (int j = tid; j < 128 * QD; j += NTHR) {
                        int c = j / QD;
                        int q = j % QD;
                        dst[j] = s_mem[q * 129 + c];   // coalesced stores, conflict-free smem
                    }
                }
                __syncthreads();
            }
        }
    }
}

extern "C" void kernel_launch(void* const* d_in, const int* in_sizes, int n_in,
                              void* d_out, int out_size) {
    const float* feat = (const float*)d_in[0];
    const float* rois = (const float*)d_in[1];
    const void*  imh  = d_in[2];
    const void*  imw  = d_in[3];
    float* out = (float*)d_out;

    int B = in_sizes[0] / (C_DIM * NPIX);
    int nrois = in_sizes[1] / 5;

    roipool_all<<<NBLK, NTHR>>>(feat, rois, imh, imw, out, B, nrois);
}